// round 9
// baseline (speedup 1.0000x reference)
#include <cuda_runtime.h>
#include <cuda_bf16.h>
#include <cuda_fp16.h>
#include <math.h>
#include <stdint.h>

// ---------------------------------------------------------------------------
// Decoder: ASPP (3x conv1x1+BN+ReLU, bilinear upsample, conv3x3+BN+ReLU)
// followed by LIIF local-ensemble query with MLP 98->128->128->1.
//
// Round 9: query N-split across CTA pairs (each CTA does 64 of 128 output
// cols; partial predictions combined by atomicAdd) -> 101KB smem, 2 CTAs/SM,
// 16 warps/SM to cover LDSM/HMMA latency. fp16 3-term everywhere.
// ---------------------------------------------------------------------------

#define HF 256
#define FC 96
#define UQ 128
#define QRES 512
#define LDC 104

__device__ float g_cat [HF*HF*FC];
__device__ float g_a4  [128*128*32];
__device__ float g_a32 [16*16*32];
__device__ float g_G   [HF*HF*UQ];
__device__ __align__(16) __half g_w1h[UQ*UQ];     // W1^T hi, row-swizzled [n][k]
__device__ __align__(16) __half g_w1l[UQ*UQ];     // W1^T lo
__device__ __align__(16) __half g_wfh[9*96*LDC];
__device__ __align__(16) __half g_wfl[9*96*LDC];
__device__ __align__(16) __half g_w0h[UQ*LDC];
__device__ __align__(16) __half g_w0l[UQ*LDC];

__device__ __forceinline__ uint32_t smem_u32(const void* p) {
    uint32_t a;
    asm("{ .reg .u64 tmp; cvta.to.shared.u64 tmp, %1; cvt.u32.u64 %0, tmp; }"
        : "=r"(a) : "l"(p));
    return a;
}

#define LDSM4(r, addr) \
    asm volatile("ldmatrix.sync.aligned.m8n8.x4.shared.b16 {%0,%1,%2,%3}, [%4];" \
        : "=r"((r)[0]), "=r"((r)[1]), "=r"((r)[2]), "=r"((r)[3]) : "r"(addr))

#define MMA16816(c, a, b0v, b1v) \
    asm volatile("mma.sync.aligned.m16n8k16.row.col.f32.f16.f16.f32 " \
        "{%0,%1,%2,%3}, {%4,%5,%6,%7}, {%8,%9}, {%0,%1,%2,%3};" \
        : "+f"((c)[0]), "+f"((c)[1]), "+f"((c)[2]), "+f"((c)[3]) \
        : "r"((a)[0]), "r"((a)[1]), "r"((a)[2]), "r"((a)[3]), \
          "r"(b0v), "r"(b1v))

__device__ __forceinline__ uint32_t packh(float a, float b) {
    __half2 h = __floats2half2_rn(a, b);
    return *(uint32_t*)&h;
}
__device__ __forceinline__ void splith4(float4 v, uint2& h, uint2& l) {
    __half h0 = __float2half_rn(v.x), h1 = __float2half_rn(v.y);
    __half h2 = __float2half_rn(v.z), h3 = __float2half_rn(v.w);
    h.x = (uint32_t)__half_as_ushort(h0) | ((uint32_t)__half_as_ushort(h1) << 16);
    h.y = (uint32_t)__half_as_ushort(h2) | ((uint32_t)__half_as_ushort(h3) << 16);
    l.x = packh(v.x - __half2float(h0), v.y - __half2float(h1));
    l.y = packh(v.z - __half2float(h2), v.w - __half2float(h3));
}
// swizzled byte offset for unpadded 256B-row fp16 tiles (K=128), chunk=16B
__device__ __forceinline__ uint32_t swz(int row, int kchunk) {
    return (uint32_t)row * 256u + (uint32_t)(((kchunk) ^ (row & 7)) << 4);
}

// ---------------------------------------------------------------------------
// fused weight-prep + out-zeroing + 1x1 convs (one launch)
// ---------------------------------------------------------------------------
#define WF_N (9*96*LDC)
#define W0_N (UQ*LDC)
#define W1_N (UQ*UQ)
#define PREP_BLKS ((WF_N + W0_N + W1_N) / 256)   // 467 exactly
#define ZERO_BLKS 1024                           // 512*512 floats

__global__ __launch_bounds__(256) void pc_kernel(
        const float* __restrict__ wf, const float* __restrict__ w0,
        const float* __restrict__ w1, float* __restrict__ outz,
        const float* __restrict__ f2, const float* __restrict__ w2,
        const float* __restrict__ s2, const float* __restrict__ b2,
        const float* __restrict__ f4, const float* __restrict__ w4,
        const float* __restrict__ s4, const float* __restrict__ b4,
        const float* __restrict__ f32, const float* __restrict__ w32,
        const float* __restrict__ s32, const float* __restrict__ b32) {
    int bid = blockIdx.x, t = threadIdx.x;
    if (bid < PREP_BLKS) {
        int i = bid * 256 + t;
        if (i < WF_N) {
            int tap = i / (96 * LDC);
            int r = i - tap * (96 * LDC);
            int co = r / LDC, ci = r - co * LDC;
            float v = (ci < 96) ? wf[((size_t)tap * 96 + ci) * 96 + co] : 0.f;
            __half h = __float2half_rn(v);
            g_wfh[i] = h; g_wfl[i] = __float2half_rn(v - __half2float(h));
        } else if (i < WF_N + W0_N) {
            int j = i - WF_N;
            int n = j / LDC, k = j - n * LDC;
            float v = (k < 96) ? w0[(size_t)k * UQ + n] : 0.f;
            __half h = __float2half_rn(v);
            g_w0h[j] = h; g_w0l[j] = __float2half_rn(v - __half2float(h));
        } else {
            int j = i - WF_N - W0_N;
            int n = j >> 7, k = j & 127;
            float v = w1[(size_t)k * UQ + n];
            __half h = __float2half_rn(v);
            int idx = n * 128 + (((k >> 3) ^ (n & 7)) << 3) + (k & 7);
            g_w1h[idx] = h; g_w1l[idx] = __float2half_rn(v - __half2float(h));
        }
        return;
    }
    int zb = bid - PREP_BLKS;
    if (zb < ZERO_BLKS) { outz[zb * 256 + t] = 0.f; return; }
    // conv1x1 part
    __shared__ float wsm[256 * 32];
    __shared__ float ssm[32], bsm[32];
    int cb = zb - ZERO_BLKS;
    const float *in, *w, *s, *b; float* out;
    int Cin, ostride, p;
    if (cb < 256) {
        in = f2; w = w2; s = s2; b = b2; out = g_cat;
        Cin = 64; ostride = 96; p = cb * 256 + t;
    } else if (cb < 320) {
        in = f4; w = w4; s = s4; b = b4; out = g_a4;
        Cin = 128; ostride = 32; p = (cb - 256) * 256 + t;
    } else {
        in = f32; w = w32; s = s32; b = b32; out = g_a32;
        Cin = 256; ostride = 32; p = (cb - 320) * 256 + t;
    }
    for (int i = t; i < Cin * 32; i += 256) wsm[i] = w[i];
    if (t < 32) { ssm[t] = s[t]; bsm[t] = b[t]; }
    __syncthreads();
    const float* ip = in + (size_t)p * Cin;
    float acc[32];
#pragma unroll
    for (int j = 0; j < 32; j++) acc[j] = 0.f;
    for (int ci = 0; ci < Cin; ci++) {
        float v = __ldg(ip + ci);
        const float* wr = wsm + ci * 32;
#pragma unroll
        for (int j = 0; j < 32; j++) acc[j] = fmaf(v, wr[j], acc[j]);
    }
    float* op = out + (size_t)p * ostride;
#pragma unroll
    for (int j = 0; j < 32; j++)
        op[j] = fmaxf(fmaf(acc[j], ssm[j], bsm[j]), 0.f);
}

// ---------------------------------------------------------------------------
// bilinear upsample into cat channels 32..95
// ---------------------------------------------------------------------------
__device__ __forceinline__ float bilerp(const float* A, int N, int c,
                                        float sy, float sx) {
    int y0 = (int)floorf(sy); float wy = sy - (float)y0;
    int x0 = (int)floorf(sx); float wx = sx - (float)x0;
    int y0c = max(y0, 0), y1c = min(y0 + 1, N - 1);
    int x0c = max(x0, 0), x1c = min(x0 + 1, N - 1);
    float v00 = A[((size_t)y0c * N + x0c) * 32 + c];
    float v01 = A[((size_t)y0c * N + x1c) * 32 + c];
    float v10 = A[((size_t)y1c * N + x0c) * 32 + c];
    float v11 = A[((size_t)y1c * N + x1c) * 32 + c];
    return (1.f - wy) * ((1.f - wx) * v00 + wx * v01)
         + wy        * ((1.f - wx) * v10 + wx * v11);
}

__global__ void upsample_kernel() {
    int idx = blockIdx.x * blockDim.x + threadIdx.x;
    if (idx >= HF * HF * 64) return;
    int c = idx & 63;
    int p = idx >> 6;
    int oy = p >> 8, ox = p & 255;
    if (c < 32) {
        float sy = (oy + 0.5f) * 0.5f - 0.5f;
        float sx = (ox + 0.5f) * 0.5f - 0.5f;
        g_cat[(size_t)p * FC + 32 + c] = bilerp(g_a4, 128, c, sy, sx);
    } else {
        int cc = c - 32;
        float sy = (oy + 0.5f) * 0.0625f - 0.5f;
        float sx = (ox + 0.5f) * 0.0625f - 0.5f;
        g_cat[(size_t)p * FC + 64 + cc] = bilerp(g_a32, 16, cc, sy, sx);
    }
}

// ---------------------------------------------------------------------------
// Fused conv3x3 + gprep. (unchanged from R8; 178us, 2 CTAs/SM)
// ---------------------------------------------------------------------------
#define CSM_R1   0
#define CSM_R1LO 37440
#define CSM_R2   74880
#define CSM_MISC 101504
#define CSM_TOTAL (101504 + 1280)
#define F_LO     26624

__global__ __launch_bounds__(256, 2)
void conv3x3g_kernel(const float* __restrict__ sf, const float* __restrict__ bf,
                     const float* __restrict__ b0) {
    extern __shared__ __align__(16) char csm[];
    uint32_t base = smem_u32(csm);
    int t = threadIdx.x, wid = t >> 5, lane = t & 31;
    int px0 = blockIdx.x * 16, py0 = blockIdx.y * 8;

    float* sfs = (float*)(csm + CSM_MISC);
    float* bfs = sfs + 96;
    float* b0s = bfs + 96;

    for (int i = t; i < 180 * 24; i += 256) {
        int pos = i / 24, c4 = (i - pos * 24) * 4;
        int hy = pos / 18, hx = pos - hy * 18;
        int gy = py0 + hy - 1, gx = px0 + hx - 1;
        float4 v = make_float4(0.f, 0.f, 0.f, 0.f);
        if ((unsigned)gy < 256u && (unsigned)gx < 256u)
            v = *(const float4*)(g_cat + ((size_t)gy * 256 + gx) * FC + c4);
        uint2 hh, ll;
        splith4(v, hh, ll);
        *(uint2*)(csm + CSM_R1 + (pos * LDC + c4) * 2) = hh;
        *(uint2*)(csm + CSM_R1LO + (pos * LDC + c4) * 2) = ll;
    }
    if (t < 96) { sfs[t] = sf[t]; bfs[t] = bf[t]; }
    if (t < 128) b0s[t] = b0[t];

    int wm = wid & 3, wn = wid >> 2;
    int arow0 = wm * 32 + (lane & 7) + ((lane >> 3) & 1) * 8;
    int acol = (lane >> 4) * 8;
    int my0 = arow0 >> 4,        mx0 = arow0 & 15;
    int my1 = (arow0 + 16) >> 4, mx1 = (arow0 + 16) & 15;
    int brow = wn * 48 + (lane & 7) + (lane >> 4) * 8;
    int bcolsel = ((lane >> 3) & 1) * 8;
    uint32_t boffB = base + CSM_R2 + (uint32_t)(brow * LDC + bcolsel) * 2;

    float accc[2][6][4];
#pragma unroll
    for (int i = 0; i < 2; i++)
#pragma unroll
        for (int j = 0; j < 6; j++)
#pragma unroll
            for (int q = 0; q < 4; q++) accc[i][j][q] = 0.f;

#pragma unroll 1
    for (int pass = 0; pass < 2; pass++) {
        const __half* wsrc = pass ? g_wfl : g_wfh;
#pragma unroll 1
        for (int tap = 0; tap < 9; tap++) {
            {
                const uint4* s1 = (const uint4*)(wsrc + tap * (96 * LDC));
                uint4* d1 = (uint4*)(csm + CSM_R2);
                for (int i = t; i < 1248; i += 256) d1[i] = s1[i];
            }
            __syncthreads();
            int ky = tap / 3, kx = tap - ky * 3;
            uint32_t aoff0 = base + CSM_R1
                + (uint32_t)(((my0 + ky) * 18 + mx0 + kx) * LDC + acol) * 2;
            uint32_t aoff1 = base + CSM_R1
                + (uint32_t)(((my1 + ky) * 18 + mx1 + kx) * LDC + acol) * 2;
#pragma unroll
            for (int kc = 0; kc < 6; kc++) {
                uint32_t k2 = kc * 32;
                uint32_t ah[2][4];
                LDSM4(ah[0], aoff0 + k2);
                LDSM4(ah[1], aoff1 + k2);
                uint32_t al[2][4];
                if (pass == 0) {
                    LDSM4(al[0], aoff0 + 37440 + k2);
                    LDSM4(al[1], aoff1 + 37440 + k2);
                }
#pragma unroll
                for (int nb = 0; nb < 3; nb++) {
                    uint32_t bo = boffB + nb * (16 * LDC * 2) + k2;
                    uint32_t bh[4];
                    LDSM4(bh, bo);
#pragma unroll
                    for (int mt = 0; mt < 2; mt++) {
                        MMA16816(accc[mt][nb*2],   ah[mt], bh[0], bh[1]);
                        MMA16816(accc[mt][nb*2+1], ah[mt], bh[2], bh[3]);
                        if (pass == 0) {
                            MMA16816(accc[mt][nb*2],   al[mt], bh[0], bh[1]);
                            MMA16816(accc[mt][nb*2+1], al[mt], bh[2], bh[3]);
                        }
                    }
                }
            }
            __syncthreads();
        }
    }

    {
        const uint4* s1 = (const uint4*)g_w0h;
        uint4* d1 = (uint4*)(csm + CSM_R2);
        for (int i = t; i < 1664; i += 256) d1[i] = s1[i];
    }
#pragma unroll
    for (int mt = 0; mt < 2; mt++)
#pragma unroll
        for (int nt = 0; nt < 6; nt++) {
            int r = wm * 32 + mt * 16 + (lane >> 2);
            int c = wn * 48 + nt * 8 + (lane & 3) * 2;
            float s0 = sfs[c], s1v = sfs[c + 1];
            float q0 = bfs[c], q1 = bfs[c + 1];
            float v0 = fmaxf(fmaf(accc[mt][nt][0], s0, q0), 0.f);
            float v1 = fmaxf(fmaf(accc[mt][nt][1], s1v, q1), 0.f);
            float v2 = fmaxf(fmaf(accc[mt][nt][2], s0, q0), 0.f);
            float v3 = fmaxf(fmaf(accc[mt][nt][3], s1v, q1), 0.f);
            __half h0 = __float2half_rn(v0), h1 = __float2half_rn(v1);
            __half h2 = __float2half_rn(v2), h3 = __float2half_rn(v3);
            uint32_t o0 = (uint32_t)(r * LDC + c) * 2;
            uint32_t o1 = (uint32_t)((r + 8) * LDC + c) * 2;
            *(uint32_t*)(csm + CSM_R1 + o0) =
                (uint32_t)__half_as_ushort(h0) | ((uint32_t)__half_as_ushort(h1) << 16);
            *(uint32_t*)(csm + CSM_R1 + o1) =
                (uint32_t)__half_as_ushort(h2) | ((uint32_t)__half_as_ushort(h3) << 16);
            *(uint32_t*)(csm + CSM_R1 + F_LO + o0) =
                packh(v0 - __half2float(h0), v1 - __half2float(h1));
            *(uint32_t*)(csm + CSM_R1 + F_LO + o1) =
                packh(v2 - __half2float(h2), v3 - __half2float(h3));
        }
    __syncthreads();

    float accg[2][8][4];
#pragma unroll
    for (int i = 0; i < 2; i++)
#pragma unroll
        for (int j = 0; j < 8; j++)
#pragma unroll
            for (int q = 0; q < 4; q++) accg[i][j][q] = 0.f;

    uint32_t gao = base + CSM_R1 + (uint32_t)(arow0 * LDC + acol) * 2;
    int gbrow = wn * 64 + (lane & 7) + (lane >> 4) * 8;
    uint32_t gbo = base + CSM_R2 + (uint32_t)(gbrow * LDC + bcolsel) * 2;

#pragma unroll
    for (int kc = 0; kc < 6; kc++) {
        uint32_t k2 = kc * 32;
        uint32_t ah[2][4], al[2][4];
        LDSM4(ah[0], gao + k2);                 LDSM4(al[0], gao + F_LO + k2);
        LDSM4(ah[1], gao + 16 * LDC * 2 + k2);  LDSM4(al[1], gao + F_LO + 16 * LDC * 2 + k2);
#pragma unroll
        for (int np = 0; np < 4; np++) {
            uint32_t bo = gbo + np * (16 * LDC * 2) + k2;
            uint32_t bh[4];
            LDSM4(bh, bo);
#pragma unroll
            for (int mt = 0; mt < 2; mt++) {
                MMA16816(accg[mt][np*2],   ah[mt], bh[0], bh[1]);
                MMA16816(accg[mt][np*2],   al[mt], bh[0], bh[1]);
                MMA16816(accg[mt][np*2+1], ah[mt], bh[2], bh[3]);
                MMA16816(accg[mt][np*2+1], al[mt], bh[2], bh[3]);
            }
        }
    }
    __syncthreads();
    {
        const uint4* s1 = (const uint4*)g_w0l;
        uint4* d1 = (uint4*)(csm + CSM_R2);
        for (int i = t; i < 1664; i += 256) d1[i] = s1[i];
    }
    __syncthreads();
#pragma unroll
    for (int kc = 0; kc < 6; kc++) {
        uint32_t k2 = kc * 32;
        uint32_t ah[2][4];
        LDSM4(ah[0], gao + k2);
        LDSM4(ah[1], gao + 16 * LDC * 2 + k2);
#pragma unroll
        for (int np = 0; np < 4; np++) {
            uint32_t bo = gbo + np * (16 * LDC * 2) + k2;
            uint32_t bl[4];
            LDSM4(bl, bo);
#pragma unroll
            for (int mt = 0; mt < 2; mt++) {
                MMA16816(accg[mt][np*2],   ah[mt], bl[0], bl[1]);
                MMA16816(accg[mt][np*2+1], ah[mt], bl[2], bl[3]);
            }
        }
    }

#pragma unroll
    for (int mt = 0; mt < 2; mt++)
#pragma unroll
        for (int nt = 0; nt < 8; nt++) {
            int r = wm * 32 + mt * 16 + (lane >> 2);
            int c = wn * 64 + nt * 8 + (lane & 3) * 2;
            size_t p0 = ((size_t)(py0 + (r >> 4)) * 256 + px0 + (r & 15)) * UQ;
            size_t p1 = ((size_t)(py0 + ((r + 8) >> 4)) * 256 + px0 + ((r + 8) & 15)) * UQ;
            *(float2*)(g_G + p0 + c) =
                make_float2(accg[mt][nt][0] + b0s[c], accg[mt][nt][1] + b0s[c + 1]);
            *(float2*)(g_G + p1 + c) =
                make_float2(accg[mt][nt][2] + b0s[c], accg[mt][nt][3] + b0s[c + 1]);
        }
}

// ---------------------------------------------------------------------------
// LIIF query kernel, N-split: each CTA computes 64 of 128 hidden cols for
// M=128 rows; partial preds combined via atomicAdd. 2 CTAs/SM, fp16 3-term.
// grid = 4096 (2048 tile-groups x 2 halves), 4 tiles per CTA.
// ---------------------------------------------------------------------------
__device__ __forceinline__ int nearest_i256(float c) {
    float f = (c + 1.0f) * 0.5f * 256.0f - 0.5f;
    int i = (int)rintf(f);
    return min(max(i, 0), 255);
}

#define QF_BH   0
#define QF_BL   16384
#define QF_AH   32768
#define QF_AL   65536
#define QF_MISC 98304
#define QSM_TOTAL (98304 + 4608)

__global__ __launch_bounds__(256, 2)
void query_ns_kernel(const float* __restrict__ coords,
                     const float* __restrict__ w0,
                     const float* __restrict__ b1,
                     const float* __restrict__ w2,
                     const float* __restrict__ b2,
                     float* __restrict__ out) {
    extern __shared__ __align__(16) char sm[];
    uint32_t base = smem_u32(sm);

    float* miscf = (float*)(sm + QF_MISC);
    float* w0r0  = miscf;              // 128
    float* w0r1  = miscf + 128;        // 128
    float* b1s   = miscf + 256;        // 64 (this half)
    float* w2s   = miscf + 320;        // 64
    float* relys = miscf + 384;        // 128
    float* relxs = miscf + 512;        // 128
    float* preds = miscf + 640;        // 128
    float* predp = miscf + 768;        // 256
    int*   ps    = (int*)(miscf + 1024);  // 128

    int t = threadIdx.x;
    int wid = t >> 5, lane = t & 31;
    int half = blockIdx.x & 1;
    int grp  = blockIdx.x >> 1;

    if (t < 128) {
        w0r0[t] = w0[96 * 128 + t];
        w0r1[t] = w0[97 * 128 + t];
    }
    if (t < 64) {
        b1s[t] = b1[half * 64 + t];
        w2s[t] = w2[half * 64 + t];
    }
    {   // this half's 64 rows of W1 hi/lo (pre-swizzled; row-local pattern)
        const uint4* s1 = (const uint4*)(g_w1h + half * 64 * 128);
        const uint4* s2 = (const uint4*)(g_w1l + half * 64 * 128);
        uint4* d1 = (uint4*)(sm + QF_BH);
        uint4* d2 = (uint4*)(sm + QF_BL);
        for (int i = t; i < 1024; i += 256) { d1[i] = s1[i]; d2[i] = s2[i]; }
    }
    float b2v = half ? 0.f : __ldg(b2);

    int wm = wid & 3, wn = wid >> 2;
    int aro = wm * 32 + (lane & 7) + ((lane >> 3) & 1) * 8;   // + mt*16
    int kchA = lane >> 4;
    int brofix = wn * 32 + (lane & 7) + (lane >> 4) * 8;      // + np*16 (local rows)
    int kchB = (lane >> 3) & 1;

    for (int it = 0; it < 4; ++it) {
        int tl = grp * 4 + it;
        int qx0 = (tl & 127) * 4, qy0 = (tl >> 7) * 8;
        __syncthreads();

        // ---- meta: 32 queries -> 128 rows ----
        if (t < 32) {
            int qy = qy0 + (t >> 2);
            int qx = qx0 + (t & 3);
            int qidx = qy * QRES + qx;
            float y = coords[qidx * 2 + 0];
            float x = coords[qidx * 2 + 1];
            const float SH_M = (float)(-1.0 / 256.0 + 1e-6);
            const float SH_P = (float)( 1.0 / 256.0 + 1e-6);
            const float CLO  = (float)(-1.0 + 1e-6);
            const float CHI  = (float)( 1.0 - 1e-6);
            float cym = fminf(fmaxf(y + SH_M, CLO), CHI);
            float cyp = fminf(fmaxf(y + SH_P, CLO), CHI);
            float cxm = fminf(fmaxf(x + SH_M, CLO), CHI);
            float cxp = fminf(fmaxf(x + SH_P, CLO), CHI);
            int iym = nearest_i256(cym), iyp = nearest_i256(cyp);
            int ixm = nearest_i256(cxm), ixp = nearest_i256(cxp);
            float relym = (y - (((iym + 0.5f) / 256.0f) * 2.0f - 1.0f)) * 256.0f;
            float relyp = (y - (((iyp + 0.5f) / 256.0f) * 2.0f - 1.0f)) * 256.0f;
            float relxm = (x - (((ixm + 0.5f) / 256.0f) * 2.0f - 1.0f)) * 256.0f;
            float relxp = (x - (((ixp + 0.5f) / 256.0f) * 2.0f - 1.0f)) * 256.0f;
            int m0 = t * 4;
            ps[m0 + 0] = iym * HF + ixm; relys[m0 + 0] = relym; relxs[m0 + 0] = relxm;
            ps[m0 + 1] = iym * HF + ixp; relys[m0 + 1] = relym; relxs[m0 + 1] = relxp;
            ps[m0 + 2] = iyp * HF + ixm; relys[m0 + 2] = relyp; relxs[m0 + 2] = relxm;
            ps[m0 + 3] = iyp * HF + ixp; relys[m0 + 3] = relyp; relxs[m0 + 3] = relxp;
        }
        __syncthreads();

        // ---- build A (H0) fp16 hi/lo (direct L2 gather; 16 warps hide it) ----
        {
            int m = t >> 1, kh = t & 1;
            int p = ps[m];
            float ry = relys[m], rx = relxs[m];
            const float4* Gr = (const float4*)(g_G + (size_t)p * UQ + kh * 64);
            const float4* WA = (const float4*)(w0r0 + kh * 64);
            const float4* WB = (const float4*)(w0r1 + kh * 64);
#pragma unroll
            for (int c = 0; c < 8; c++) {
                float4 g0 = __ldg(Gr + 2 * c), g1 = __ldg(Gr + 2 * c + 1);
                float4 a0 = WA[2 * c], a1 = WA[2 * c + 1];
                float4 q0 = WB[2 * c], q1 = WB[2 * c + 1];
                float v[8];
                v[0] = fmaxf(g0.x + ry * a0.x + rx * q0.x, 0.f);
                v[1] = fmaxf(g0.y + ry * a0.y + rx * q0.y, 0.f);
                v[2] = fmaxf(g0.z + ry * a0.z + rx * q0.z, 0.f);
                v[3] = fmaxf(g0.w + ry * a0.w + rx * q0.w, 0.f);
                v[4] = fmaxf(g1.x + ry * a1.x + rx * q1.x, 0.f);
                v[5] = fmaxf(g1.y + ry * a1.y + rx * q1.y, 0.f);
                v[6] = fmaxf(g1.z + ry * a1.z + rx * q1.z, 0.f);
                v[7] = fmaxf(g1.w + ry * a1.w + rx * q1.w, 0.f);
                uint32_t hv[4], lv[4];
#pragma unroll
                for (int j = 0; j < 4; j++) {
                    float x0 = v[2 * j], x1 = v[2 * j + 1];
                    __half h0 = __float2half_rn(x0);
                    __half h1 = __float2half_rn(x1);
                    hv[j] = (uint32_t)__half_as_ushort(h0)
                          | ((uint32_t)__half_as_ushort(h1) << 16);
                    lv[j] = packh(x0 - __half2float(h0), x1 - __half2float(h1));
                }
                uint32_t adr = swz(m, kh * 8 + c);
                *(uint4*)(sm + QF_AH + adr) = make_uint4(hv[0], hv[1], hv[2], hv[3]);
                *(uint4*)(sm + QF_AL + adr) = make_uint4(lv[0], lv[1], lv[2], lv[3]);
            }
        }
        __syncthreads();

        // ---- GEMM: warp m32 x n32(local), fp16 3-term ----
        float acc[2][4][4];
#pragma unroll
        for (int i = 0; i < 2; i++)
#pragma unroll
            for (int j = 0; j < 4; j++)
#pragma unroll
                for (int q = 0; q < 4; q++) acc[i][j][q] = 0.f;

#pragma unroll
        for (int k0 = 0; k0 < 128; k0 += 16) {
            int kc = k0 >> 3;
            uint32_t ah[2][4], al[2][4];
#pragma unroll
            for (int mt = 0; mt < 2; mt++) {
                uint32_t adrA = base + swz(aro + mt * 16, kc + kchA);
                LDSM4(ah[mt], adrA + QF_AH);
                LDSM4(al[mt], adrA + QF_AL);
            }
#pragma unroll
            for (int np = 0; np < 2; np++) {
                uint32_t adrB = base + swz(brofix + np * 16, kc + kchB);
                uint32_t bh[4], bl[4];
                LDSM4(bh, adrB + QF_BH);
                LDSM4(bl, adrB + QF_BL);
#pragma unroll
                for (int mt = 0; mt < 2; mt++) {
                    MMA16816(acc[mt][np * 2],     ah[mt], bh[0], bh[1]);
                    MMA16816(acc[mt][np * 2],     al[mt], bh[0], bh[1]);
                    MMA16816(acc[mt][np * 2],     ah[mt], bl[0], bl[1]);
                    MMA16816(acc[mt][np * 2 + 1], ah[mt], bh[2], bh[3]);
                    MMA16816(acc[mt][np * 2 + 1], al[mt], bh[2], bh[3]);
                    MMA16816(acc[mt][np * 2 + 1], ah[mt], bl[2], bl[3]);
                }
            }
        }

        // ---- epilogue: relu(+b1) dot w2 over this half's 32 cols/warp ----
#pragma unroll
        for (int mt = 0; mt < 2; mt++) {
            float pA = 0.f, pB = 0.f;
#pragma unroll
            for (int nt = 0; nt < 4; nt++) {
                int c0 = wn * 32 + nt * 8 + (lane & 3) * 2;   // local col
                float ba = b1s[c0], bb = b1s[c0 + 1];
                float wa = w2s[c0], wb = w2s[c0 + 1];
                pA = fmaf(fmaxf(acc[mt][nt][0] + ba, 0.f), wa, pA);
                pA = fmaf(fmaxf(acc[mt][nt][1] + bb, 0.f), wb, pA);
                pB = fmaf(fmaxf(acc[mt][nt][2] + ba, 0.f), wa, pB);
                pB = fmaf(fmaxf(acc[mt][nt][3] + bb, 0.f), wb, pB);
            }
            pA += __shfl_xor_sync(0xFFFFFFFF, pA, 1);
            pA += __shfl_xor_sync(0xFFFFFFFF, pA, 2);
            pB += __shfl_xor_sync(0xFFFFFFFF, pB, 1);
            pB += __shfl_xor_sync(0xFFFFFFFF, pB, 2);
            if ((lane & 3) == 0) {
                int r = wm * 32 + mt * 16 + (lane >> 2);
                predp[r * 2 + wn] = pA;
                predp[(r + 8) * 2 + wn] = pB;
            }
        }
        __syncthreads();
        if (t < 128) preds[t] = predp[2 * t] + predp[2 * t + 1] + b2v;
        __syncthreads();

        // ---- blend partial (diagonal area swap) + atomic combine ----
        if (t < 32) {
            int qy = qy0 + (t >> 2);
            int qx = qx0 + (t & 3);
            int m0 = t * 4;
            float a0 = fabsf(relys[m0 + 0] * relxs[m0 + 0]) + 1e-9f;
            float a1 = fabsf(relys[m0 + 1] * relxs[m0 + 1]) + 1e-9f;
            float a2 = fabsf(relys[m0 + 2] * relxs[m0 + 2]) + 1e-9f;
            float a3 = fabsf(relys[m0 + 3] * relxs[m0 + 3]) + 1e-9f;
            float num = preds[m0 + 0] * a3 + preds[m0 + 1] * a2
                      + preds[m0 + 2] * a1 + preds[m0 + 3] * a0;
            atomicAdd(out + qy * QRES + qx, num / (a0 + a1 + a2 + a3));
        }
    }
}

// ---------------------------------------------------------------------------
extern "C" void kernel_launch(void* const* d_in, const int* in_sizes, int n_in,
                              void* d_out, int out_size) {
    const float* feats2  = (const float*)d_in[0];
    const float* feats4  = (const float*)d_in[1];
    const float* feats32 = (const float*)d_in[2];
    const float* coords  = (const float*)d_in[3];
    const float* w2c  = (const float*)d_in[4];
    const float* s2c  = (const float*)d_in[5];
    const float* b2c  = (const float*)d_in[6];
    const float* w4c  = (const float*)d_in[7];
    const float* s4c  = (const float*)d_in[8];
    const float* b4c  = (const float*)d_in[9];
    const float* w32c = (const float*)d_in[10];
    const float* s32c = (const float*)d_in[11];
    const float* b32c = (const float*)d_in[12];
    const float* wf   = (const float*)d_in[13];
    const float* sf   = (const float*)d_in[14];
    const float* bf   = (const float*)d_in[15];
    const float* mw0  = (const float*)d_in[16];
    const float* mb0  = (const float*)d_in[17];
    const float* mw1  = (const float*)d_in[18];
    const float* mb1  = (const float*)d_in[19];
    const float* mw2  = (const float*)d_in[20];
    const float* mb2  = (const float*)d_in[21];
    float* out = (float*)d_out;

    // 4 launches; raw ncu idx = my idx + 2 -> slot 5 = query kernel
    pc_kernel<<<PREP_BLKS + ZERO_BLKS + 321, 256>>>(wf, mw0, mw1, out,
                                        feats2, w2c, s2c, b2c,
                                        feats4, w4c, s4c, b4c,
                                        feats32, w32c, s32c, b32c);        // 0
    upsample_kernel<<<(256 * 256 * 64) / 256, 256>>>();                    // 1

    cudaFuncSetAttribute(conv3x3g_kernel, cudaFuncAttributeMaxDynamicSharedMemorySize,
                         CSM_TOTAL);
    conv3x3g_kernel<<<dim3(16, 32), 256, CSM_TOTAL>>>(sf, bf, mb0);        // 2

    cudaFuncSetAttribute(query_ns_kernel, cudaFuncAttributeMaxDynamicSharedMemorySize,
                         QSM_TOTAL);
    query_ns_kernel<<<4096, 256, QSM_TOTAL>>>(coords, mw0, mb1, mw2, mb2, out);  // 3

    (void)in_sizes; (void)n_in; (void)out_size;
}

// round 12
// speedup vs baseline: 1.2323x; 1.2323x over previous
#include <cuda_runtime.h>
#include <cuda_bf16.h>
#include <cuda_fp16.h>
#include <math.h>
#include <stdint.h>

// ---------------------------------------------------------------------------
// Decoder: ASPP (3x conv1x1+BN+ReLU, bilinear upsample, conv3x3+BN+ReLU)
// followed by LIIF local-ensemble query with MLP 98->128->128->1.
//
// Round 11: Round 10 design with the smem overflow fixed (misc region was
// 4096B but only 3584B allocated). Query GEMM = 2-pass weight hi/lo split
// (A single fp16): halved A-traffic, -33% MMAs, 84.5KB smem, 2 CTAs/SM.
// conv3x3+gprep stay fp16 3-term.
// ---------------------------------------------------------------------------

#define HF 256
#define FC 96
#define UQ 128
#define QRES 512
#define LDC 104

__device__ float g_cat [HF*HF*FC];
__device__ float g_a4  [128*128*32];
__device__ float g_a32 [16*16*32];
__device__ float g_G   [HF*HF*UQ];
__device__ __align__(16) __half g_w1h[UQ*UQ];     // W1^T hi, row-swizzled [n][k]
__device__ __align__(16) __half g_w1l[UQ*UQ];     // W1^T lo, row-swizzled
__device__ __align__(16) __half g_wfh[9*96*LDC];
__device__ __align__(16) __half g_wfl[9*96*LDC];
__device__ __align__(16) __half g_w0h[UQ*LDC];
__device__ __align__(16) __half g_w0l[UQ*LDC];

__device__ __forceinline__ uint32_t smem_u32(const void* p) {
    uint32_t a;
    asm("{ .reg .u64 tmp; cvta.to.shared.u64 tmp, %1; cvt.u32.u64 %0, tmp; }"
        : "=r"(a) : "l"(p));
    return a;
}

#define LDSM4(r, addr) \
    asm volatile("ldmatrix.sync.aligned.m8n8.x4.shared.b16 {%0,%1,%2,%3}, [%4];" \
        : "=r"((r)[0]), "=r"((r)[1]), "=r"((r)[2]), "=r"((r)[3]) : "r"(addr))

#define MMA16816(c, a, b0v, b1v) \
    asm volatile("mma.sync.aligned.m16n8k16.row.col.f32.f16.f16.f32 " \
        "{%0,%1,%2,%3}, {%4,%5,%6,%7}, {%8,%9}, {%0,%1,%2,%3};" \
        : "+f"((c)[0]), "+f"((c)[1]), "+f"((c)[2]), "+f"((c)[3]) \
        : "r"((a)[0]), "r"((a)[1]), "r"((a)[2]), "r"((a)[3]), \
          "r"(b0v), "r"(b1v))

__device__ __forceinline__ uint32_t packh(float a, float b) {
    __half2 h = __floats2half2_rn(a, b);
    return *(uint32_t*)&h;
}
__device__ __forceinline__ void splith4(float4 v, uint2& h, uint2& l) {
    __half h0 = __float2half_rn(v.x), h1 = __float2half_rn(v.y);
    __half h2 = __float2half_rn(v.z), h3 = __float2half_rn(v.w);
    h.x = (uint32_t)__half_as_ushort(h0) | ((uint32_t)__half_as_ushort(h1) << 16);
    h.y = (uint32_t)__half_as_ushort(h2) | ((uint32_t)__half_as_ushort(h3) << 16);
    l.x = packh(v.x - __half2float(h0), v.y - __half2float(h1));
    l.y = packh(v.z - __half2float(h2), v.w - __half2float(h3));
}
// swizzled byte offset for unpadded 256B-row fp16 tiles (K=128), chunk=16B
__device__ __forceinline__ uint32_t swz(int row, int kchunk) {
    return (uint32_t)row * 256u + (uint32_t)(((kchunk) ^ (row & 7)) << 4);
}

// ---------------------------------------------------------------------------
// fused weight-prep + 1x1 convs (one launch)
// ---------------------------------------------------------------------------
#define WF_N (9*96*LDC)
#define W0_N (UQ*LDC)
#define W1_N (UQ*UQ)
#define PREP_BLKS ((WF_N + W0_N + W1_N) / 256)   // 467 exactly

__global__ __launch_bounds__(256) void pc_kernel(
        const float* __restrict__ wf, const float* __restrict__ w0,
        const float* __restrict__ w1,
        const float* __restrict__ f2, const float* __restrict__ w2,
        const float* __restrict__ s2, const float* __restrict__ b2,
        const float* __restrict__ f4, const float* __restrict__ w4,
        const float* __restrict__ s4, const float* __restrict__ b4,
        const float* __restrict__ f32, const float* __restrict__ w32,
        const float* __restrict__ s32, const float* __restrict__ b32) {
    int bid = blockIdx.x, t = threadIdx.x;
    if (bid < PREP_BLKS) {
        int i = bid * 256 + t;
        if (i < WF_N) {
            int tap = i / (96 * LDC);
            int r = i - tap * (96 * LDC);
            int co = r / LDC, ci = r - co * LDC;
            float v = (ci < 96) ? wf[((size_t)tap * 96 + ci) * 96 + co] : 0.f;
            __half h = __float2half_rn(v);
            g_wfh[i] = h; g_wfl[i] = __float2half_rn(v - __half2float(h));
        } else if (i < WF_N + W0_N) {
            int j = i - WF_N;
            int n = j / LDC, k = j - n * LDC;
            float v = (k < 96) ? w0[(size_t)k * UQ + n] : 0.f;
            __half h = __float2half_rn(v);
            g_w0h[j] = h; g_w0l[j] = __float2half_rn(v - __half2float(h));
        } else {
            int j = i - WF_N - W0_N;
            int n = j >> 7, k = j & 127;
            float v = w1[(size_t)k * UQ + n];
            __half h = __float2half_rn(v);
            int idx = n * 128 + (((k >> 3) ^ (n & 7)) << 3) + (k & 7);
            g_w1h[idx] = h; g_w1l[idx] = __float2half_rn(v - __half2float(h));
        }
        return;
    }
    // conv1x1 part
    __shared__ float wsm[256 * 32];
    __shared__ float ssm[32], bsm[32];
    int cb = bid - PREP_BLKS;
    const float *in, *w, *s, *b; float* out;
    int Cin, ostride, p;
    if (cb < 256) {
        in = f2; w = w2; s = s2; b = b2; out = g_cat;
        Cin = 64; ostride = 96; p = cb * 256 + t;
    } else if (cb < 320) {
        in = f4; w = w4; s = s4; b = b4; out = g_a4;
        Cin = 128; ostride = 32; p = (cb - 256) * 256 + t;
    } else {
        in = f32; w = w32; s = s32; b = b32; out = g_a32;
        Cin = 256; ostride = 32; p = (cb - 320) * 256 + t;
    }
    for (int i = t; i < Cin * 32; i += 256) wsm[i] = w[i];
    if (t < 32) { ssm[t] = s[t]; bsm[t] = b[t]; }
    __syncthreads();
    const float* ip = in + (size_t)p * Cin;
    float acc[32];
#pragma unroll
    for (int j = 0; j < 32; j++) acc[j] = 0.f;
    for (int ci = 0; ci < Cin; ci++) {
        float v = __ldg(ip + ci);
        const float* wr = wsm + ci * 32;
#pragma unroll
        for (int j = 0; j < 32; j++) acc[j] = fmaf(v, wr[j], acc[j]);
    }
    float* op = out + (size_t)p * ostride;
#pragma unroll
    for (int j = 0; j < 32; j++)
        op[j] = fmaxf(fmaf(acc[j], ssm[j], bsm[j]), 0.f);
}

// ---------------------------------------------------------------------------
// bilinear upsample into cat channels 32..95
// ---------------------------------------------------------------------------
__device__ __forceinline__ float bilerp(const float* A, int N, int c,
                                        float sy, float sx) {
    int y0 = (int)floorf(sy); float wy = sy - (float)y0;
    int x0 = (int)floorf(sx); float wx = sx - (float)x0;
    int y0c = max(y0, 0), y1c = min(y0 + 1, N - 1);
    int x0c = max(x0, 0), x1c = min(x0 + 1, N - 1);
    float v00 = A[((size_t)y0c * N + x0c) * 32 + c];
    float v01 = A[((size_t)y0c * N + x1c) * 32 + c];
    float v10 = A[((size_t)y1c * N + x0c) * 32 + c];
    float v11 = A[((size_t)y1c * N + x1c) * 32 + c];
    return (1.f - wy) * ((1.f - wx) * v00 + wx * v01)
         + wy        * ((1.f - wx) * v10 + wx * v11);
}

__global__ void upsample_kernel() {
    int idx = blockIdx.x * blockDim.x + threadIdx.x;
    if (idx >= HF * HF * 64) return;
    int c = idx & 63;
    int p = idx >> 6;
    int oy = p >> 8, ox = p & 255;
    if (c < 32) {
        float sy = (oy + 0.5f) * 0.5f - 0.5f;
        float sx = (ox + 0.5f) * 0.5f - 0.5f;
        g_cat[(size_t)p * FC + 32 + c] = bilerp(g_a4, 128, c, sy, sx);
    } else {
        int cc = c - 32;
        float sy = (oy + 0.5f) * 0.0625f - 0.5f;
        float sx = (ox + 0.5f) * 0.0625f - 0.5f;
        g_cat[(size_t)p * FC + 64 + cc] = bilerp(g_a32, 16, cc, sy, sx);
    }
}

// ---------------------------------------------------------------------------
// Fused conv3x3 + gprep (fp16 3-term, two weight passes; 2 CTAs/SM).
// ---------------------------------------------------------------------------
#define CSM_R1   0
#define CSM_R1LO 37440
#define CSM_R2   74880
#define CSM_MISC 101504
#define CSM_TOTAL (101504 + 1280)
#define F_LO     26624

__global__ __launch_bounds__(256, 2)
void conv3x3g_kernel(const float* __restrict__ sf, const float* __restrict__ bf,
                     const float* __restrict__ b0) {
    extern __shared__ __align__(16) char csm[];
    uint32_t base = smem_u32(csm);
    int t = threadIdx.x, wid = t >> 5, lane = t & 31;
    int px0 = blockIdx.x * 16, py0 = blockIdx.y * 8;

    float* sfs = (float*)(csm + CSM_MISC);
    float* bfs = sfs + 96;
    float* b0s = bfs + 96;

    for (int i = t; i < 180 * 24; i += 256) {
        int pos = i / 24, c4 = (i - pos * 24) * 4;
        int hy = pos / 18, hx = pos - hy * 18;
        int gy = py0 + hy - 1, gx = px0 + hx - 1;
        float4 v = make_float4(0.f, 0.f, 0.f, 0.f);
        if ((unsigned)gy < 256u && (unsigned)gx < 256u)
            v = *(const float4*)(g_cat + ((size_t)gy * 256 + gx) * FC + c4);
        uint2 hh, ll;
        splith4(v, hh, ll);
        *(uint2*)(csm + CSM_R1 + (pos * LDC + c4) * 2) = hh;
        *(uint2*)(csm + CSM_R1LO + (pos * LDC + c4) * 2) = ll;
    }
    if (t < 96) { sfs[t] = sf[t]; bfs[t] = bf[t]; }
    if (t < 128) b0s[t] = b0[t];

    int wm = wid & 3, wn = wid >> 2;
    int arow0 = wm * 32 + (lane & 7) + ((lane >> 3) & 1) * 8;
    int acol = (lane >> 4) * 8;
    int my0 = arow0 >> 4,        mx0 = arow0 & 15;
    int my1 = (arow0 + 16) >> 4, mx1 = (arow0 + 16) & 15;
    int brow = wn * 48 + (lane & 7) + (lane >> 4) * 8;
    int bcolsel = ((lane >> 3) & 1) * 8;
    uint32_t boffB = base + CSM_R2 + (uint32_t)(brow * LDC + bcolsel) * 2;

    float accc[2][6][4];
#pragma unroll
    for (int i = 0; i < 2; i++)
#pragma unroll
        for (int j = 0; j < 6; j++)
#pragma unroll
            for (int q = 0; q < 4; q++) accc[i][j][q] = 0.f;

#pragma unroll 1
    for (int pass = 0; pass < 2; pass++) {
        const __half* wsrc = pass ? g_wfl : g_wfh;
#pragma unroll 1
        for (int tap = 0; tap < 9; tap++) {
            {
                const uint4* s1 = (const uint4*)(wsrc + tap * (96 * LDC));
                uint4* d1 = (uint4*)(csm + CSM_R2);
                for (int i = t; i < 1248; i += 256) d1[i] = s1[i];
            }
            __syncthreads();
            int ky = tap / 3, kx = tap - ky * 3;
            uint32_t aoff0 = base + CSM_R1
                + (uint32_t)(((my0 + ky) * 18 + mx0 + kx) * LDC + acol) * 2;
            uint32_t aoff1 = base + CSM_R1
                + (uint32_t)(((my1 + ky) * 18 + mx1 + kx) * LDC + acol) * 2;
#pragma unroll
            for (int kc = 0; kc < 6; kc++) {
                uint32_t k2 = kc * 32;
                uint32_t ah[2][4];
                LDSM4(ah[0], aoff0 + k2);
                LDSM4(ah[1], aoff1 + k2);
                uint32_t al[2][4];
                if (pass == 0) {
                    LDSM4(al[0], aoff0 + 37440 + k2);
                    LDSM4(al[1], aoff1 + 37440 + k2);
                }
#pragma unroll
                for (int nb = 0; nb < 3; nb++) {
                    uint32_t bo = boffB + nb * (16 * LDC * 2) + k2;
                    uint32_t bh[4];
                    LDSM4(bh, bo);
#pragma unroll
                    for (int mt = 0; mt < 2; mt++) {
                        MMA16816(accc[mt][nb*2],   ah[mt], bh[0], bh[1]);
                        MMA16816(accc[mt][nb*2+1], ah[mt], bh[2], bh[3]);
                        if (pass == 0) {
                            MMA16816(accc[mt][nb*2],   al[mt], bh[0], bh[1]);
                            MMA16816(accc[mt][nb*2+1], al[mt], bh[2], bh[3]);
                        }
                    }
                }
            }
            __syncthreads();
        }
    }

    {
        const uint4* s1 = (const uint4*)g_w0h;
        uint4* d1 = (uint4*)(csm + CSM_R2);
        for (int i = t; i < 1664; i += 256) d1[i] = s1[i];
    }
#pragma unroll
    for (int mt = 0; mt < 2; mt++)
#pragma unroll
        for (int nt = 0; nt < 6; nt++) {
            int r = wm * 32 + mt * 16 + (lane >> 2);
            int c = wn * 48 + nt * 8 + (lane & 3) * 2;
            float s0 = sfs[c], s1v = sfs[c + 1];
            float q0 = bfs[c], q1 = bfs[c + 1];
            float v0 = fmaxf(fmaf(accc[mt][nt][0], s0, q0), 0.f);
            float v1 = fmaxf(fmaf(accc[mt][nt][1], s1v, q1), 0.f);
            float v2 = fmaxf(fmaf(accc[mt][nt][2], s0, q0), 0.f);
            float v3 = fmaxf(fmaf(accc[mt][nt][3], s1v, q1), 0.f);
            __half h0 = __float2half_rn(v0), h1 = __float2half_rn(v1);
            __half h2 = __float2half_rn(v2), h3 = __float2half_rn(v3);
            uint32_t o0 = (uint32_t)(r * LDC + c) * 2;
            uint32_t o1 = (uint32_t)((r + 8) * LDC + c) * 2;
            *(uint32_t*)(csm + CSM_R1 + o0) =
                (uint32_t)__half_as_ushort(h0) | ((uint32_t)__half_as_ushort(h1) << 16);
            *(uint32_t*)(csm + CSM_R1 + o1) =
                (uint32_t)__half_as_ushort(h2) | ((uint32_t)__half_as_ushort(h3) << 16);
            *(uint32_t*)(csm + CSM_R1 + F_LO + o0) =
                packh(v0 - __half2float(h0), v1 - __half2float(h1));
            *(uint32_t*)(csm + CSM_R1 + F_LO + o1) =
                packh(v2 - __half2float(h2), v3 - __half2float(h3));
        }
    __syncthreads();

    float accg[2][8][4];
#pragma unroll
    for (int i = 0; i < 2; i++)
#pragma unroll
        for (int j = 0; j < 8; j++)
#pragma unroll
            for (int q = 0; q < 4; q++) accg[i][j][q] = 0.f;

    uint32_t gao = base + CSM_R1 + (uint32_t)(arow0 * LDC + acol) * 2;
    int gbrow = wn * 64 + (lane & 7) + (lane >> 4) * 8;
    uint32_t gbo = base + CSM_R2 + (uint32_t)(gbrow * LDC + bcolsel) * 2;

#pragma unroll
    for (int kc = 0; kc < 6; kc++) {
        uint32_t k2 = kc * 32;
        uint32_t ah[2][4], al[2][4];
        LDSM4(ah[0], gao + k2);                 LDSM4(al[0], gao + F_LO + k2);
        LDSM4(ah[1], gao + 16 * LDC * 2 + k2);  LDSM4(al[1], gao + F_LO + 16 * LDC * 2 + k2);
#pragma unroll
        for (int np = 0; np < 4; np++) {
            uint32_t bo = gbo + np * (16 * LDC * 2) + k2;
            uint32_t bh[4];
            LDSM4(bh, bo);
#pragma unroll
            for (int mt = 0; mt < 2; mt++) {
                MMA16816(accg[mt][np*2],   ah[mt], bh[0], bh[1]);
                MMA16816(accg[mt][np*2],   al[mt], bh[0], bh[1]);
                MMA16816(accg[mt][np*2+1], ah[mt], bh[2], bh[3]);
                MMA16816(accg[mt][np*2+1], al[mt], bh[2], bh[3]);
            }
        }
    }
    __syncthreads();
    {
        const uint4* s1 = (const uint4*)g_w0l;
        uint4* d1 = (uint4*)(csm + CSM_R2);
        for (int i = t; i < 1664; i += 256) d1[i] = s1[i];
    }
    __syncthreads();
#pragma unroll
    for (int kc = 0; kc < 6; kc++) {
        uint32_t k2 = kc * 32;
        uint32_t ah[2][4];
        LDSM4(ah[0], gao + k2);
        LDSM4(ah[1], gao + 16 * LDC * 2 + k2);
#pragma unroll
        for (int np = 0; np < 4; np++) {
            uint32_t bo = gbo + np * (16 * LDC * 2) + k2;
            uint32_t bl[4];
            LDSM4(bl, bo);
#pragma unroll
            for (int mt = 0; mt < 2; mt++) {
                MMA16816(accg[mt][np*2],   ah[mt], bl[0], bl[1]);
                MMA16816(accg[mt][np*2+1], ah[mt], bl[2], bl[3]);
            }
        }
    }

#pragma unroll
    for (int mt = 0; mt < 2; mt++)
#pragma unroll
        for (int nt = 0; nt < 8; nt++) {
            int r = wm * 32 + mt * 16 + (lane >> 2);
            int c = wn * 64 + nt * 8 + (lane & 3) * 2;
            size_t p0 = ((size_t)(py0 + (r >> 4)) * 256 + px0 + (r & 15)) * UQ;
            size_t p1 = ((size_t)(py0 + ((r + 8) >> 4)) * 256 + px0 + ((r + 8) & 15)) * UQ;
            *(float2*)(g_G + p0 + c) =
                make_float2(accg[mt][nt][0] + b0s[c], accg[mt][nt][1] + b0s[c + 1]);
            *(float2*)(g_G + p1 + c) =
                make_float2(accg[mt][nt][2] + b0s[c], accg[mt][nt][3] + b0s[c + 1]);
        }
}

// ---------------------------------------------------------------------------
// LIIF query kernel: M=64 tiles, A single fp16, B = W1 hi/lo (weight split).
// acc += A*Bh + A*Bl. Warp tile m32 x n32. 84.5KB smem -> 2 CTAs/SM.
// 2048 CTAs x 8 tiles.
// ---------------------------------------------------------------------------
__device__ __forceinline__ int nearest_i256(float c) {
    float f = (c + 1.0f) * 0.5f * 256.0f - 0.5f;
    int i = (int)rintf(f);
    return min(max(i, 0), 255);
}

#define QW_A    0
#define QW_BH   16384
#define QW_BL   49152
#define QW_MISC 81920
#define QSM_TOTAL (81920 + 4608)   // misc region is 4096B used; pad to 4608

__global__ __launch_bounds__(256, 2)
void query_ws_kernel(const float* __restrict__ coords,
                     const float* __restrict__ w0,
                     const float* __restrict__ b1,
                     const float* __restrict__ w2,
                     const float* __restrict__ b2,
                     float* __restrict__ out) {
    extern __shared__ __align__(16) char sm[];
    uint32_t base = smem_u32(sm);

    float* miscf = (float*)(sm + QW_MISC);
    float* w0r0  = miscf;             // 128
    float* w0r1  = miscf + 128;       // 128
    float* b1s   = miscf + 256;       // 128
    float* w2s   = miscf + 384;       // 128
    float* relys = miscf + 512;       // 64
    float* relxs = miscf + 576;       // 64
    float* preds = miscf + 640;       // 64
    float* predp = miscf + 704;       // 256  [row][wn]
    int*   ps    = (int*)(miscf + 960);   // 64  (total 1024 words = 4096B)

    int t = threadIdx.x;
    int wid = t >> 5, lane = t & 31;

    if (t < 128) {
        w0r0[t] = w0[96 * 128 + t];
        w0r1[t] = w0[97 * 128 + t];
        b1s[t]  = b1[t];
        w2s[t]  = w2[t];
    }
    {   // W1 hi/lo (pre-swizzled) -> smem, once
        const uint4* s1 = (const uint4*)g_w1h;
        const uint4* s2 = (const uint4*)g_w1l;
        uint4* d1 = (uint4*)(sm + QW_BH);
        uint4* d2 = (uint4*)(sm + QW_BL);
        for (int i = t; i < 2048; i += 256) { d1[i] = s1[i]; d2[i] = s2[i]; }
    }
    float b2v = __ldg(b2);

    // warp tile: wm (0..1) -> 32 M-rows, wn (0..3) -> 32 N-cols
    int wm = wid & 1, wn = wid >> 1;
    int aro = wm * 32 + (lane & 7) + ((lane >> 3) & 1) * 8;   // + mt*16
    int kchA = lane >> 4;
    int bro = wn * 32 + (lane & 7) + (lane >> 4) * 8;         // + np*16
    int kchB = (lane >> 3) & 1;

    for (int it = 0; it < 8; ++it) {
        int tl = blockIdx.x * 8 + it;
        int qx0 = (tl & 127) * 4, qy0 = (tl >> 7) * 4;
        __syncthreads();

        // ---- meta: 16 queries -> 64 rows ----
        if (t < 16) {
            int qy = qy0 + (t >> 2);
            int qx = qx0 + (t & 3);
            int qidx = qy * QRES + qx;
            float y = coords[qidx * 2 + 0];
            float x = coords[qidx * 2 + 1];
            const float SH_M = (float)(-1.0 / 256.0 + 1e-6);
            const float SH_P = (float)( 1.0 / 256.0 + 1e-6);
            const float CLO  = (float)(-1.0 + 1e-6);
            const float CHI  = (float)( 1.0 - 1e-6);
            float cym = fminf(fmaxf(y + SH_M, CLO), CHI);
            float cyp = fminf(fmaxf(y + SH_P, CLO), CHI);
            float cxm = fminf(fmaxf(x + SH_M, CLO), CHI);
            float cxp = fminf(fmaxf(x + SH_P, CLO), CHI);
            int iym = nearest_i256(cym), iyp = nearest_i256(cyp);
            int ixm = nearest_i256(cxm), ixp = nearest_i256(cxp);
            float relym = (y - (((iym + 0.5f) / 256.0f) * 2.0f - 1.0f)) * 256.0f;
            float relyp = (y - (((iyp + 0.5f) / 256.0f) * 2.0f - 1.0f)) * 256.0f;
            float relxm = (x - (((ixm + 0.5f) / 256.0f) * 2.0f - 1.0f)) * 256.0f;
            float relxp = (x - (((ixp + 0.5f) / 256.0f) * 2.0f - 1.0f)) * 256.0f;
            int m0 = t * 4;
            ps[m0 + 0] = iym * HF + ixm; relys[m0 + 0] = relym; relxs[m0 + 0] = relxm;
            ps[m0 + 1] = iym * HF + ixp; relys[m0 + 1] = relym; relxs[m0 + 1] = relxp;
            ps[m0 + 2] = iyp * HF + ixm; relys[m0 + 2] = relyp; relxs[m0 + 2] = relxm;
            ps[m0 + 3] = iyp * HF + ixp; relys[m0 + 3] = relyp; relxs[m0 + 3] = relxp;
        }
        __syncthreads();

        // ---- build A (H0) single fp16, swizzled: 64 rows x 128 k ----
        {
            int m = t >> 2, kq = (t & 3) * 32;
            int p = ps[m];
            float ry = relys[m], rx = relxs[m];
            const float4* Gr = (const float4*)(g_G + (size_t)p * UQ + kq);
            const float4* WA = (const float4*)(w0r0 + kq);
            const float4* WB = (const float4*)(w0r1 + kq);
#pragma unroll
            for (int c = 0; c < 4; c++) {
                float4 g0 = __ldg(Gr + 2 * c), g1 = __ldg(Gr + 2 * c + 1);
                float4 a0 = WA[2 * c], a1 = WA[2 * c + 1];
                float4 q0 = WB[2 * c], q1 = WB[2 * c + 1];
                uint32_t hv[4];
                hv[0] = packh(fmaxf(g0.x + ry * a0.x + rx * q0.x, 0.f),
                              fmaxf(g0.y + ry * a0.y + rx * q0.y, 0.f));
                hv[1] = packh(fmaxf(g0.z + ry * a0.z + rx * q0.z, 0.f),
                              fmaxf(g0.w + ry * a0.w + rx * q0.w, 0.f));
                hv[2] = packh(fmaxf(g1.x + ry * a1.x + rx * q1.x, 0.f),
                              fmaxf(g1.y + ry * a1.y + rx * q1.y, 0.f));
                hv[3] = packh(fmaxf(g1.z + ry * a1.z + rx * q1.z, 0.f),
                              fmaxf(g1.w + ry * a1.w + rx * q1.w, 0.f));
                uint32_t adr = swz(m, (kq >> 3) + c);
                *(uint4*)(sm + QW_A + adr) = make_uint4(hv[0], hv[1], hv[2], hv[3]);
            }
        }
        __syncthreads();

        // ---- GEMM: acc += A*Bh + A*Bl, warp m32 x n32 ----
        float acc[2][4][4];
#pragma unroll
        for (int i = 0; i < 2; i++)
#pragma unroll
            for (int j = 0; j < 4; j++)
#pragma unroll
                for (int q = 0; q < 4; q++) acc[i][j][q] = 0.f;

#pragma unroll
        for (int k0 = 0; k0 < 128; k0 += 16) {
            int kc = k0 >> 3;
            uint32_t ah[2][4];
#pragma unroll
            for (int mt = 0; mt < 2; mt++)
                LDSM4(ah[mt], base + QW_A + swz(aro + mt * 16, kc + kchA));
#pragma unroll
            for (int np = 0; np < 2; np++) {
                uint32_t adrB = base + swz(bro + np * 16, kc + kchB);
                uint32_t bh[4], bl[4];
                LDSM4(bh, adrB + QW_BH);
                LDSM4(bl, adrB + QW_BL);
#pragma unroll
                for (int mt = 0; mt < 2; mt++) {
                    MMA16816(acc[mt][np * 2],     ah[mt], bh[0], bh[1]);
                    MMA16816(acc[mt][np * 2],     ah[mt], bl[0], bl[1]);
                    MMA16816(acc[mt][np * 2 + 1], ah[mt], bh[2], bh[3]);
                    MMA16816(acc[mt][np * 2 + 1], ah[mt], bl[2], bl[3]);
                }
            }
        }

        // ---- epilogue: relu(+b1) dot w2 over this warp's 32 cols ----
#pragma unroll
        for (int mt = 0; mt < 2; mt++) {
            float pA = 0.f, pB = 0.f;
#pragma unroll
            for (int nt = 0; nt < 4; nt++) {
                int c0 = wn * 32 + nt * 8 + (lane & 3) * 2;
                float ba = b1s[c0], bb = b1s[c0 + 1];
                float wa = w2s[c0], wb = w2s[c0 + 1];
                pA = fmaf(fmaxf(acc[mt][nt][0] + ba, 0.f), wa, pA);
                pA = fmaf(fmaxf(acc[mt][nt][1] + bb, 0.f), wb, pA);
                pB = fmaf(fmaxf(acc[mt][nt][2] + ba, 0.f), wa, pB);
                pB = fmaf(fmaxf(acc[mt][nt][3] + bb, 0.f), wb, pB);
            }
            pA += __shfl_xor_sync(0xFFFFFFFF, pA, 1);
            pA += __shfl_xor_sync(0xFFFFFFFF, pA, 2);
            pB += __shfl_xor_sync(0xFFFFFFFF, pB, 1);
            pB += __shfl_xor_sync(0xFFFFFFFF, pB, 2);
            if ((lane & 3) == 0) {
                int r = wm * 32 + mt * 16 + (lane >> 2);
                predp[r * 4 + wn] = pA;
                predp[(r + 8) * 4 + wn] = pB;
            }
        }
        __syncthreads();
        if (t < 64)
            preds[t] = predp[4 * t] + predp[4 * t + 1]
                     + predp[4 * t + 2] + predp[4 * t + 3] + b2v;
        __syncthreads();

        // ---- blend (diagonal area swap) ----
        if (t < 16) {
            int qy = qy0 + (t >> 2);
            int qx = qx0 + (t & 3);
            int m0 = t * 4;
            float a0 = fabsf(relys[m0 + 0] * relxs[m0 + 0]) + 1e-9f;
            float a1 = fabsf(relys[m0 + 1] * relxs[m0 + 1]) + 1e-9f;
            float a2 = fabsf(relys[m0 + 2] * relxs[m0 + 2]) + 1e-9f;
            float a3 = fabsf(relys[m0 + 3] * relxs[m0 + 3]) + 1e-9f;
            float num = preds[m0 + 0] * a3 + preds[m0 + 1] * a2
                      + preds[m0 + 2] * a1 + preds[m0 + 3] * a0;
            out[qy * QRES + qx] = num / (a0 + a1 + a2 + a3);
        }
    }
}

// ---------------------------------------------------------------------------
extern "C" void kernel_launch(void* const* d_in, const int* in_sizes, int n_in,
                              void* d_out, int out_size) {
    const float* feats2  = (const float*)d_in[0];
    const float* feats4  = (const float*)d_in[1];
    const float* feats32 = (const float*)d_in[2];
    const float* coords  = (const float*)d_in[3];
    const float* w2c  = (const float*)d_in[4];
    const float* s2c  = (const float*)d_in[5];
    const float* b2c  = (const float*)d_in[6];
    const float* w4c  = (const float*)d_in[7];
    const float* s4c  = (const float*)d_in[8];
    const float* b4c  = (const float*)d_in[9];
    const float* w32c = (const float*)d_in[10];
    const float* s32c = (const float*)d_in[11];
    const float* b32c = (const float*)d_in[12];
    const float* wf   = (const float*)d_in[13];
    const float* sf   = (const float*)d_in[14];
    const float* bf   = (const float*)d_in[15];
    const float* mw0  = (const float*)d_in[16];
    const float* mb0  = (const float*)d_in[17];
    const float* mw1  = (const float*)d_in[18];
    const float* mb1  = (const float*)d_in[19];
    const float* mw2  = (const float*)d_in[20];
    const float* mb2  = (const float*)d_in[21];
    float* out = (float*)d_out;

    // 4 launches; raw ncu idx = my idx + 2 -> slot 5 = query kernel
    pc_kernel<<<PREP_BLKS + 321, 256>>>(wf, mw0, mw1,
                                        feats2, w2c, s2c, b2c,
                                        feats4, w4c, s4c, b4c,
                                        feats32, w32c, s32c, b32c);        // 0
    upsample_kernel<<<(256 * 256 * 64) / 256, 256>>>();                    // 1

    cudaFuncSetAttribute(conv3x3g_kernel, cudaFuncAttributeMaxDynamicSharedMemorySize,
                         CSM_TOTAL);
    conv3x3g_kernel<<<dim3(16, 32), 256, CSM_TOTAL>>>(sf, bf, mb0);        // 2

    cudaFuncSetAttribute(query_ws_kernel, cudaFuncAttributeMaxDynamicSharedMemorySize,
                         QSM_TOTAL);
    query_ws_kernel<<<2048, 256, QSM_TOTAL>>>(coords, mw0, mb1, mw2, mb2, out);  // 3

    (void)in_sizes; (void)n_in; (void)out_size;
}